// round 8
// baseline (speedup 1.0000x reference)
#include <cuda_runtime.h>
#include <cuda_bf16.h>
#include <cstdint>

// ---------------------------------------------------------------------------
// out[n] = (segment_sum(pred_prob[src], dst)[n] - 1)^2 * special_cost[n]
// N = 1,000,000 nodes, E = 16,000,000 edges.
//
// v7: 2-launch pipeline (scatter -> apply+reset) on a zero-initialized
// __device__ scratch. Scatter: 4 edges/thread (measured-best), gather via
// __ldcg (L2-only; 4MB table never fits 228KB L1, skip L1 fill overhead),
// atomicAdd -> RED. Apply: 8 elems/thread, front-batched float4 pairs to
// cover L2 latency (R7 profile showed issue=9%, ~2x above its traffic floor).
//
// Bottleneck model (calibrated R2/R3/R7): scatter ~123us, bound by the
// shared L1tex/LSU path: ~60us gather wavefronts + ~77us spread-RED lanes.
// ---------------------------------------------------------------------------

#define MAX_NODES 1000000
__device__ float g_accum[MAX_NODES];   // static zero-init

__global__ __launch_bounds__(256) void scatter_accum_kernel(
        const float* __restrict__ pred_prob,
        const int*   __restrict__ src,
        const int*   __restrict__ dst,
        int num_edges) {
    int i = blockIdx.x * blockDim.x + threadIdx.x;
    int base = i * 4;
    if (base + 3 < num_edges) {
        int4 s4 = *reinterpret_cast<const int4*>(src + base);
        int4 d4 = *reinterpret_cast<const int4*>(dst + base);
        float m0 = __ldcg(pred_prob + s4.x);   // L2-only gather
        float m1 = __ldcg(pred_prob + s4.y);
        float m2 = __ldcg(pred_prob + s4.z);
        float m3 = __ldcg(pred_prob + s4.w);
        atomicAdd(g_accum + d4.x, m0);         // return unused -> RED
        atomicAdd(g_accum + d4.y, m1);
        atomicAdd(g_accum + d4.z, m2);
        atomicAdd(g_accum + d4.w, m3);
    } else {
        for (int e = base; e < num_edges; ++e) {
            atomicAdd(g_accum + dst[e], __ldcg(pred_prob + src[e]));
        }
    }
}

// Reads accumulated sums, computes (a-1)^2 * cost into out, and resets the
// accumulator to zero so the next (graph-replayed) call starts clean.
// 8 elements per thread, loads front-batched for MLP.
__global__ __launch_bounds__(256) void apply_reset_kernel(
        const float* __restrict__ special_cost,
        float*       __restrict__ out,
        int n) {
    int i = blockIdx.x * blockDim.x + threadIdx.x;
    int base = i * 8;
    if (base + 7 < n) {
        const float4* ap = reinterpret_cast<const float4*>(g_accum + base);
        const float4* cp = reinterpret_cast<const float4*>(special_cost + base);
        float4 a0 = ap[0];
        float4 a1 = ap[1];
        float4 c0 = cp[0];
        float4 c1 = cp[1];
        float4 r0, r1;
        float h;
        h = a0.x - 1.0f; r0.x = h * h * c0.x;
        h = a0.y - 1.0f; r0.y = h * h * c0.y;
        h = a0.z - 1.0f; r0.z = h * h * c0.z;
        h = a0.w - 1.0f; r0.w = h * h * c0.w;
        h = a1.x - 1.0f; r1.x = h * h * c1.x;
        h = a1.y - 1.0f; r1.y = h * h * c1.y;
        h = a1.z - 1.0f; r1.z = h * h * c1.z;
        h = a1.w - 1.0f; r1.w = h * h * c1.w;
        float4* op = reinterpret_cast<float4*>(out + base);
        op[0] = r0;
        op[1] = r1;
        float4* zp = reinterpret_cast<float4*>(g_accum + base);
        float4 z = make_float4(0.0f, 0.0f, 0.0f, 0.0f);
        zp[0] = z;
        zp[1] = z;
    } else {
        for (int k = base; k < n; ++k) {
            float h = g_accum[k] - 1.0f;
            out[k] = h * h * special_cost[k];
            g_accum[k] = 0.0f;
        }
    }
}

// Fallback path (N > MAX_NODES): classic init/scatter/apply on d_out.
__global__ __launch_bounds__(256) void init_kernel(float* __restrict__ out, int n) {
    int i = blockIdx.x * blockDim.x + threadIdx.x;
    int base = i * 4;
    if (base + 3 < n) {
        *reinterpret_cast<float4*>(out + base) =
            make_float4(-1.0f, -1.0f, -1.0f, -1.0f);
    } else {
        for (int k = base; k < n; ++k) out[k] = -1.0f;
    }
}

__global__ __launch_bounds__(256) void scatter_out_kernel(
        const float* __restrict__ pred_prob,
        const int*   __restrict__ src,
        const int*   __restrict__ dst,
        float*       __restrict__ out,
        int num_edges) {
    int i = blockIdx.x * blockDim.x + threadIdx.x;
    int base = i * 4;
    if (base + 3 < num_edges) {
        int4 s4 = *reinterpret_cast<const int4*>(src + base);
        int4 d4 = *reinterpret_cast<const int4*>(dst + base);
        atomicAdd(out + d4.x, __ldcg(pred_prob + s4.x));
        atomicAdd(out + d4.y, __ldcg(pred_prob + s4.y));
        atomicAdd(out + d4.z, __ldcg(pred_prob + s4.z));
        atomicAdd(out + d4.w, __ldcg(pred_prob + s4.w));
    } else {
        for (int e = base; e < num_edges; ++e) {
            atomicAdd(out + dst[e], __ldcg(pred_prob + src[e]));
        }
    }
}

__global__ __launch_bounds__(256) void apply_inplace_kernel(
        float* __restrict__ out,
        const float* __restrict__ special_cost,
        int n) {
    int i = blockIdx.x * blockDim.x + threadIdx.x;
    int base = i * 4;
    if (base + 3 < n) {
        float4 h = *reinterpret_cast<const float4*>(out + base);
        float4 c = *reinterpret_cast<const float4*>(special_cost + base);
        h.x = h.x * h.x * c.x;
        h.y = h.y * h.y * c.y;
        h.z = h.z * h.z * c.z;
        h.w = h.w * h.w * c.w;
        *reinterpret_cast<float4*>(out + base) = h;
    } else {
        for (int k = base; k < n; ++k) {
            float h = out[k];
            out[k] = h * h * special_cost[k];
        }
    }
}

extern "C" void kernel_launch(void* const* d_in, const int* in_sizes, int n_in,
                              void* d_out, int out_size) {
    const float* pred_prob    = (const float*)d_in[0];
    const float* special_cost = (const float*)d_in[1];
    const int*   src          = (const int*)d_in[2];
    const int*   dst          = (const int*)d_in[3];
    float*       out          = (float*)d_out;

    const int N = in_sizes[0];
    const int E = in_sizes[2];

    const int threads = 256;
    int eblocks = ((E + 3) / 4 + threads - 1) / threads;

    if (N <= MAX_NODES) {
        int nblocks8 = ((N + 7) / 8 + threads - 1) / threads;
        scatter_accum_kernel<<<eblocks, threads>>>(pred_prob, src, dst, E);
        apply_reset_kernel<<<nblocks8, threads>>>(special_cost, out, N);
    } else {
        int nblocks = ((N + 3) / 4 + threads - 1) / threads;
        init_kernel<<<nblocks, threads>>>(out, N);
        scatter_out_kernel<<<eblocks, threads>>>(pred_prob, src, dst, out, E);
        apply_inplace_kernel<<<nblocks, threads>>>(out, special_cost, N);
    }
}

// round 10
// speedup vs baseline: 1.0141x; 1.0141x over previous
#include <cuda_runtime.h>
#include <cuda_bf16.h>
#include <cstdint>

// ---------------------------------------------------------------------------
// out[n] = (segment_sum(pred_prob[src], dst)[n] - 1)^2 * special_cost[n]
// N = 1,000,000 nodes, E = 16,000,000 edges.
//
// v9 (resubmitted after infra failure): 2-launch pipeline
// (scatter -> apply+reset) on zero-initialized __device__ scratch.
// Scatter: 2 edges/thread (batching trend: 8->135us, 4->129us; testing 2),
// __ldg gather (measured better than __ldcg), atomicAdd -> RED.
// Apply: 4 elems/thread (measured-best: 6.27us vs 6.69us at 8/thread).
//
// Bottleneck model (calibrated R2/R3/R7/R8): scatter ~122us = ~70us
// spread-RED (1.29 cyc/lane) + ~54us gather wavefronts, serialized on the
// shared LSU/L1tex path. smem privatization loses (spread ATOMS = 2 cyc/lane
// > REDG 1.29). Remaining structural lever: TMA gather4 (held in reserve).
// ---------------------------------------------------------------------------

#define MAX_NODES 1000000
__device__ float g_accum[MAX_NODES];   // static zero-init

__global__ __launch_bounds__(256) void scatter_accum_kernel(
        const float* __restrict__ pred_prob,
        const int*   __restrict__ src,
        const int*   __restrict__ dst,
        int num_edges) {
    int i = blockIdx.x * blockDim.x + threadIdx.x;
    int base = i * 2;
    if (base + 1 < num_edges) {
        int2 s2 = *reinterpret_cast<const int2*>(src + base);
        int2 d2 = *reinterpret_cast<const int2*>(dst + base);
        float m0 = __ldg(pred_prob + s2.x);
        float m1 = __ldg(pred_prob + s2.y);
        atomicAdd(g_accum + d2.x, m0);   // return unused -> RED
        atomicAdd(g_accum + d2.y, m1);
    } else if (base < num_edges) {
        atomicAdd(g_accum + dst[base], __ldg(pred_prob + src[base]));
    }
}

// Reads accumulated sums, computes (a-1)^2 * cost into out, and resets the
// accumulator to zero so the next (graph-replayed) call starts clean.
__global__ __launch_bounds__(256) void apply_reset_kernel(
        const float* __restrict__ special_cost,
        float*       __restrict__ out,
        int n) {
    int i = blockIdx.x * blockDim.x + threadIdx.x;
    int base = i * 4;
    if (base + 3 < n) {
        float4 a = *reinterpret_cast<const float4*>(g_accum + base);
        float4 c = *reinterpret_cast<const float4*>(special_cost + base);
        float4 r;
        float h;
        h = a.x - 1.0f; r.x = h * h * c.x;
        h = a.y - 1.0f; r.y = h * h * c.y;
        h = a.z - 1.0f; r.z = h * h * c.z;
        h = a.w - 1.0f; r.w = h * h * c.w;
        *reinterpret_cast<float4*>(out + base) = r;
        *reinterpret_cast<float4*>(g_accum + base) =
            make_float4(0.0f, 0.0f, 0.0f, 0.0f);
    } else {
        for (int k = base; k < n; ++k) {
            float h = g_accum[k] - 1.0f;
            out[k] = h * h * special_cost[k];
            g_accum[k] = 0.0f;
        }
    }
}

// Fallback path (N > MAX_NODES): classic init/scatter/apply on d_out.
__global__ __launch_bounds__(256) void init_kernel(float* __restrict__ out, int n) {
    int i = blockIdx.x * blockDim.x + threadIdx.x;
    int base = i * 4;
    if (base + 3 < n) {
        *reinterpret_cast<float4*>(out + base) =
            make_float4(-1.0f, -1.0f, -1.0f, -1.0f);
    } else {
        for (int k = base; k < n; ++k) out[k] = -1.0f;
    }
}

__global__ __launch_bounds__(256) void scatter_out_kernel(
        const float* __restrict__ pred_prob,
        const int*   __restrict__ src,
        const int*   __restrict__ dst,
        float*       __restrict__ out,
        int num_edges) {
    int i = blockIdx.x * blockDim.x + threadIdx.x;
    int base = i * 2;
    if (base + 1 < num_edges) {
        int2 s2 = *reinterpret_cast<const int2*>(src + base);
        int2 d2 = *reinterpret_cast<const int2*>(dst + base);
        atomicAdd(out + d2.x, __ldg(pred_prob + s2.x));
        atomicAdd(out + d2.y, __ldg(pred_prob + s2.y));
    } else if (base < num_edges) {
        atomicAdd(out + dst[base], __ldg(pred_prob + src[base]));
    }
}

__global__ __launch_bounds__(256) void apply_inplace_kernel(
        float* __restrict__ out,
        const float* __restrict__ special_cost,
        int n) {
    int i = blockIdx.x * blockDim.x + threadIdx.x;
    int base = i * 4;
    if (base + 3 < n) {
        float4 h = *reinterpret_cast<const float4*>(out + base);
        float4 c = *reinterpret_cast<const float4*>(special_cost + base);
        h.x = h.x * h.x * c.x;
        h.y = h.y * h.y * c.y;
        h.z = h.z * h.z * c.z;
        h.w = h.w * h.w * c.w;
        *reinterpret_cast<float4*>(out + base) = h;
    } else {
        for (int k = base; k < n; ++k) {
            float h = out[k];
            out[k] = h * h * special_cost[k];
        }
    }
}

extern "C" void kernel_launch(void* const* d_in, const int* in_sizes, int n_in,
                              void* d_out, int out_size) {
    const float* pred_prob    = (const float*)d_in[0];
    const float* special_cost = (const float*)d_in[1];
    const int*   src          = (const int*)d_in[2];
    const int*   dst          = (const int*)d_in[3];
    float*       out          = (float*)d_out;

    const int N = in_sizes[0];
    const int E = in_sizes[2];

    const int threads = 256;
    int eblocks = ((E + 1) / 2 + threads - 1) / threads;
    int nblocks = ((N + 3) / 4 + threads - 1) / threads;

    if (N <= MAX_NODES) {
        scatter_accum_kernel<<<eblocks, threads>>>(pred_prob, src, dst, E);
        apply_reset_kernel<<<nblocks, threads>>>(special_cost, out, N);
    } else {
        init_kernel<<<nblocks, threads>>>(out, N);
        scatter_out_kernel<<<eblocks, threads>>>(pred_prob, src, dst, out, E);
        apply_inplace_kernel<<<nblocks, threads>>>(out, special_cost, N);
    }
}